// round 8
// baseline (speedup 1.0000x reference)
#include <cuda_runtime.h>
#include <cuda_fp16.h>
#include <math.h>
#include <stdint.h>

// ---------------- problem constants -----------------------------------------
#define NTOK 4096
#define HD   1024
#define NE   8
#define FD   4096
#define NSLOT (NTOK * 2)

// ---------------- GEMM tiling (fp16 mma.sync + ldmatrix + cp.async) ----------
#define BM 128
#define BN 128
#define BK 64
#define STAGES 3
#define NTHR 256

// dynamic smem layout (bytes); stage = A 16KB + B 16KB
#define SM_A    0                        // STAGES x 128x64 fp16 = 3 x 16384
#define SM_B    (STAGES * 16384)         // STAGES x 64x128 fp16 = 3 x 16384
#define SM_BIAS (SM_B + STAGES * 16384)  // 98304 ; 128 fp32
#define SMEM_BYTES (SM_BIAS + 512)       // 98816  (2 CTAs/SM -> ~198KB)

// ---------------- scratch (device globals; no allocations) -------------------
__device__ __align__(128) __half g_xh[(size_t)NTOK * HD];
__device__ __align__(128) __half g_w1h[(size_t)NE * HD * FD];
__device__ __align__(128) __half g_w2h[(size_t)NE * FD * HD];
__device__ __align__(128) __half g_h[(size_t)NSLOT * FD];
__device__ float  g_y[(size_t)NSLOT * HD];
__device__ int    g_tok_of_slot[NSLOT];
__device__ int    g_slot_of_tok[NSLOT];
__device__ int    g_expert_of_tok[NSLOT];
__device__ float  g_gate_of_tok[NSLOT];
__device__ int    g_counts[NE];

// ---------------- helpers ----------------------------------------------------
__device__ __forceinline__ uint32_t smem_u32(const void* p) {
    uint32_t a;
    asm("{ .reg .u64 t; cvta.to.shared.u64 t, %1; cvt.u32.u64 %0, t; }" : "=r"(a) : "l"(p));
    return a;
}

__device__ __forceinline__ void cp16(uint32_t dst, const void* src) {
    asm volatile("cp.async.cg.shared.global [%0], [%1], 16;" :: "r"(dst), "l"(src));
}
__device__ __forceinline__ void cp_commit() {
    asm volatile("cp.async.commit_group;" ::: "memory");
}
__device__ __forceinline__ void cp_wait1() {
    asm volatile("cp.async.wait_group 1;" ::: "memory");
}

__device__ __forceinline__ void ldsm4(uint32_t r[4], uint32_t addr) {
    asm volatile("ldmatrix.sync.aligned.m8n8.x4.shared.b16 {%0,%1,%2,%3}, [%4];"
                 : "=r"(r[0]), "=r"(r[1]), "=r"(r[2]), "=r"(r[3]) : "r"(addr));
}
__device__ __forceinline__ void ldsm4t(uint32_t r[4], uint32_t addr) {
    asm volatile("ldmatrix.sync.aligned.m8n8.x4.trans.shared.b16 {%0,%1,%2,%3}, [%4];"
                 : "=r"(r[0]), "=r"(r[1]), "=r"(r[2]), "=r"(r[3]) : "r"(addr));
}

__device__ __forceinline__ void mma16816(float c[4], const uint32_t a[4],
                                         uint32_t b0, uint32_t b1) {
    asm volatile(
        "mma.sync.aligned.m16n8k16.row.col.f32.f16.f16.f32 "
        "{%0,%1,%2,%3}, {%4,%5,%6,%7}, {%8,%9}, {%0,%1,%2,%3};\n"
        : "+f"(c[0]), "+f"(c[1]), "+f"(c[2]), "+f"(c[3])
        : "r"(a[0]), "r"(a[1]), "r"(a[2]), "r"(a[3]), "r"(b0), "r"(b1));
}

__device__ __forceinline__ float gelu_exact(float x) {
    return 0.5f * x * (1.0f + erff(x * 0.70710678118654752440f));
}

// ---------------- stage 1: weight fp16 pre-convert (+zero counts) ------------
__global__ void cvt_kernel(const float* __restrict__ W1,
                           const float* __restrict__ W2) {
    if (blockIdx.x == 0 && blockIdx.y == 0 && threadIdx.x < NE)
        g_counts[threadIdx.x] = 0;
    const float* src = blockIdx.y ? W2 : W1;
    __half* dst = blockIdx.y ? g_w2h : g_w1h;
    const size_t n4 = (size_t)NE * HD * FD / 4;
    const size_t stride = (size_t)gridDim.x * blockDim.x;
    for (size_t i = blockIdx.x * blockDim.x + threadIdx.x; i < n4; i += stride) {
        float4 v = ((const float4*)src)[i];
        __half2 h0 = __floats2half2_rn(v.x, v.y);
        __half2 h1 = __floats2half2_rn(v.z, v.w);
        uint2 u = make_uint2(*(uint32_t*)&h0, *(uint32_t*)&h1);
        ((uint2*)dst)[i] = u;
    }
}

// ---------------- stage 2: router (+ x fp16 convert) -------------------------
__global__ void router_kernel(const float* __restrict__ x,
                              const float* __restrict__ Wr) {
    const int t = blockIdx.x;
    __shared__ float sx[HD];
    __shared__ float slog[NE];

    const float* xr = x + (size_t)t * HD;
    for (int i = threadIdx.x; i < HD; i += blockDim.x) {
        const float v = xr[i];
        sx[i] = v;
        g_xh[(size_t)t * HD + i] = __float2half_rn(v);
    }
    __syncthreads();

    const int w = threadIdx.x >> 5, lane = threadIdx.x & 31;
    if (w < NE) {
        const float* wr = Wr + (size_t)w * HD;
        float s = 0.f;
        for (int i = lane; i < HD; i += 32) s += sx[i] * wr[i];
        #pragma unroll
        for (int o = 16; o > 0; o >>= 1) s += __shfl_xor_sync(0xffffffffu, s, o);
        if (lane == 0) slog[w] = s;
    }
    __syncthreads();

    if (threadIdx.x == 0) {
        int i0 = 0; float v0 = slog[0];
        #pragma unroll
        for (int e = 1; e < NE; e++) if (slog[e] > v0) { v0 = slog[e]; i0 = e; }
        int i1 = -1; float v1 = -INFINITY;
        #pragma unroll
        for (int e = 0; e < NE; e++) {
            if (e == i0) continue;
            if (slog[e] > v1) { v1 = slog[e]; i1 = e; }
        }
        float e1 = expf(v1 - v0);
        float inv = 1.f / (1.f + e1);
        g_expert_of_tok[t * 2 + 0] = i0; g_gate_of_tok[t * 2 + 0] = inv;
        g_expert_of_tok[t * 2 + 1] = i1; g_gate_of_tok[t * 2 + 1] = e1 * inv;
        atomicAdd(&g_counts[i0], 1);
        atomicAdd(&g_counts[i1], 1);
    }
}

// ---------------- stage 3: compaction (offsets fused) ------------------------
__global__ void build_kernel() {
    const int e = blockIdx.x;
    __shared__ int warp_sums[32];
    int base = 0;
    #pragma unroll
    for (int i = 0; i < NE; i++) if (i < e) base += g_counts[i];
    const int lane = threadIdx.x & 31, w = threadIdx.x >> 5;

    for (int t0 = 0; t0 < NTOK; t0 += 1024) {
        const int t = t0 + threadIdx.x;
        int k = -1;
        if (g_expert_of_tok[t * 2 + 0] == e) k = 0;
        else if (g_expert_of_tok[t * 2 + 1] == e) k = 1;
        const int flag = (k >= 0) ? 1 : 0;

        const unsigned bal = __ballot_sync(0xffffffffu, flag);
        const int pre = __popc(bal & ((1u << lane) - 1u));
        if (lane == 0) warp_sums[w] = __popc(bal);
        __syncthreads();
        int woff = 0, total = 0;
        #pragma unroll
        for (int i = 0; i < 32; i++) {
            if (i < w) woff += warp_sums[i];
            total += warp_sums[i];
        }
        if (flag) {
            const int slot = base + woff + pre;
            g_tok_of_slot[slot] = t;
            g_slot_of_tok[t * 2 + k] = slot;
        }
        base += total;
        __syncthreads();
    }
}

// ---------------- stage 4/5: routed fp16 GEMM, BK=64, 2 CTAs/SM --------------
// FIRST=true : g_h(fp16) = gelu(g_xh[gather] @ W1h[e] + b1[e])   K=HD,  N=FD
// FIRST=false: g_y(fp32) = g_h[contig] @ W2h[e]                  K=FD,  N=HD
template <bool FIRST>
__global__ __launch_bounds__(NTHR, 2) void moe_mma(const float* __restrict__ bias) {
    constexpr int KDIM = FIRST ? HD : FD;
    constexpr int NDIM = FIRST ? FD : HD;
    constexpr int NKT  = KDIM / BK;      // 16 or 64

    const int e  = blockIdx.z;
    const int ne = g_counts[e];
    const int m0 = blockIdx.y * BM;
    if (m0 >= ne) return;
    const int n0 = blockIdx.x * BN;
    int off = 0;
    #pragma unroll
    for (int i = 0; i < NE; i++) if (i < e) off += g_counts[i];

    extern __shared__ char smem[];
    const uint32_t sb = smem_u32(smem);
    const int tid = threadIdx.x;

    if (FIRST && tid < 32)
        ((float4*)(smem + SM_BIAS))[tid] =
            ((const float4*)(bias + (size_t)e * NDIM + n0))[tid];

    const __half* Ab = FIRST ? g_xh : g_h;
    const __half* Wb = (FIRST ? g_w1h : g_w2h) + (size_t)e * KDIM * NDIM;

    // ---- cp.async staging maps ----
    // A tile 128 rows x 64 halves (128B rows, 8 granules). thread -> row tid&127,
    // half-of-row tid>>7; 4 granules each: g = half*4 + j.
    const int ra = tid & 127, ha = tid >> 7;
    int ga = m0 + ra; if (ga > ne - 1) ga = ne - 1;
    const int rowid = FIRST ? g_tok_of_slot[off + ga] : (off + ga);
    const __half* asrc = Ab + (size_t)rowid * KDIM + ha * 32;
    uint32_t ad[4];
    #pragma unroll
    for (int j = 0; j < 4; j++)
        ad[j] = (uint32_t)(ra * 128 + (((ha * 4 + j) ^ (ra & 7)) * 16));

    // B tile 64 rows x 128 halves (256B rows, 16 granules). thread -> row tid&63,
    // segment tid>>6; 4 granules each: g = seg*4 + j.
    const int rb = tid & 63, sg = tid >> 6;
    const __half* bsrc = Wb + (size_t)rb * NDIM + n0 + sg * 32;
    uint32_t bd[4];
    #pragma unroll
    for (int j = 0; j < 4; j++)
        bd[j] = (uint32_t)(rb * 256 + (((sg * 4 + j) ^ (rb & 7)) * 16));

    // ---- ldmatrix fragment maps: warp grid 2(M) x 4(N), warp tile 64x32 ----
    const int w = tid >> 5, lane = tid & 31;
    const int wm = w & 1, wn = w >> 1;
    const int l16 = lane & 15, lh = lane >> 4;
    const int sel = l16 & 7;
    // A: addr = abase[mi] + xo[ks]
    uint32_t abase[4], xo[4];
    #pragma unroll
    for (int mi = 0; mi < 4; mi++)
        abase[mi] = (uint32_t)((wm * 64 + mi * 16 + l16) * 128);
    #pragma unroll
    for (int ks = 0; ks < 4; ks++)
        xo[ks] = (uint32_t)(((2 * ks + lh) ^ sel) * 16);
    // B: addr = ks*4096 + binner[nb]
    uint32_t binner[2];
    #pragma unroll
    for (int nb = 0; nb < 2; nb++)
        binner[nb] = (uint32_t)(l16 * 256 + (((wn * 4 + nb * 2 + lh) ^ sel) * 16));

    float acc[4][4][4];
    #pragma unroll
    for (int mi = 0; mi < 4; mi++)
        #pragma unroll
        for (int ni = 0; ni < 4; ni++)
            #pragma unroll
            for (int q = 0; q < 4; q++) acc[mi][ni][q] = 0.f;

    auto issue_stage = [&](int kt) {
        const int stg = kt % STAGES;
        const uint32_t sa  = sb + SM_A + stg * 16384;
        const uint32_t sbm = sb + SM_B + stg * 16384;
        const __half* ap = asrc + (size_t)kt * BK;
        const __half* bp = bsrc + (size_t)kt * BK * NDIM;
        #pragma unroll
        for (int j = 0; j < 4; j++) cp16(sa + ad[j], ap + j * 8);
        #pragma unroll
        for (int j = 0; j < 4; j++) cp16(sbm + bd[j], bp + j * 8);
    };

    // ---- prologue: fill 2 stages ----
    issue_stage(0); cp_commit();
    issue_stage(1); cp_commit();

    // ---- mainloop ----
    #pragma unroll 1
    for (int kt = 0; kt < NKT; kt++) {
        cp_wait1();
        __syncthreads();

        if (kt + 2 < NKT) issue_stage(kt + 2);
        cp_commit();

        const int stg = kt % STAGES;
        const uint32_t sA = sb + SM_A + stg * 16384;
        const uint32_t sB = sb + SM_B + stg * 16384;
        #pragma unroll
        for (int ks = 0; ks < 4; ks++) {
            uint32_t af[4][4], bf[2][4];
            ldsm4 (af[0], sA + abase[0] + xo[ks]);
            ldsm4 (af[1], sA + abase[1] + xo[ks]);
            ldsm4 (af[2], sA + abase[2] + xo[ks]);
            ldsm4 (af[3], sA + abase[3] + xo[ks]);
            ldsm4t(bf[0], sB + ks * 4096 + binner[0]);
            ldsm4t(bf[1], sB + ks * 4096 + binner[1]);
            #pragma unroll
            for (int nb = 0; nb < 2; nb++) {
                #pragma unroll
                for (int mi = 0; mi < 4; mi++) {
                    mma16816(acc[mi][nb * 2 + 0], af[mi], bf[nb][0], bf[nb][1]);
                    mma16816(acc[mi][nb * 2 + 1], af[mi], bf[nb][2], bf[nb][3]);
                }
            }
        }
    }

    // ---- epilogue ----
    const int rbase = wm * 64 + (lane >> 2);
    const int cbase = wn * 32 + (lane & 3) * 2;
    #pragma unroll
    for (int mi = 0; mi < 4; mi++) {
        #pragma unroll
        for (int hrow = 0; hrow < 2; hrow++) {
            const int mloc = rbase + mi * 16 + hrow * 8;
            const int grow = m0 + mloc;
            if (grow >= ne) continue;
            #pragma unroll
            for (int ni = 0; ni < 4; ni++) {
                const int cr = cbase + ni * 8;
                float v0 = acc[mi][ni][hrow * 2 + 0];
                float v1 = acc[mi][ni][hrow * 2 + 1];
                if (FIRST) {
                    const float2 bv = *(const float2*)(smem + SM_BIAS + cr * 4);
                    v0 = gelu_exact(v0 + bv.x);
                    v1 = gelu_exact(v1 + bv.y);
                    __half2 hv = __floats2half2_rn(v0, v1);
                    *(__half2*)(g_h + (size_t)(off + grow) * NDIM + n0 + cr) = hv;
                } else {
                    *(float2*)(g_y + (size_t)(off + grow) * NDIM + n0 + cr) =
                        make_float2(v0, v1);
                }
            }
        }
    }
}

// ---------------- stage 6: gated combine -------------------------------------
__global__ void combine_kernel(const float* __restrict__ b2,
                               float* __restrict__ out) {
    const int t  = blockIdx.x;
    const int e0 = g_expert_of_tok[t * 2 + 0], e1 = g_expert_of_tok[t * 2 + 1];
    const float gg0 = g_gate_of_tok[t * 2 + 0], gg1 = g_gate_of_tok[t * 2 + 1];
    const int s0 = g_slot_of_tok[t * 2 + 0], s1 = g_slot_of_tok[t * 2 + 1];

    const float4* y0  = (const float4*)(g_y + (size_t)s0 * HD);
    const float4* y1  = (const float4*)(g_y + (size_t)s1 * HD);
    const float4* bb0 = (const float4*)(b2 + (size_t)e0 * HD);
    const float4* bb1 = (const float4*)(b2 + (size_t)e1 * HD);
    float4* o = (float4*)(out + (size_t)t * HD);

    for (int i = threadIdx.x; i < HD / 4; i += blockDim.x) {
        const float4 a = y0[i], b = y1[i], c = bb0[i], d = bb1[i];
        float4 rr;
        rr.x = gg0 * (a.x + c.x) + gg1 * (b.x + d.x);
        rr.y = gg0 * (a.y + c.y) + gg1 * (b.y + d.y);
        rr.z = gg0 * (a.z + c.z) + gg1 * (b.z + d.z);
        rr.w = gg0 * (a.w + c.w) + gg1 * (b.w + d.w);
        o[i] = rr;
    }
}

// ---------------- launch ------------------------------------------------------
extern "C" void kernel_launch(void* const* d_in, const int* in_sizes, int n_in,
                              void* d_out, int out_size) {
    const float* x  = (const float*)d_in[0];
    const float* Wr = (const float*)d_in[1];
    const float* W1 = (const float*)d_in[2];
    const float* b1 = (const float*)d_in[3];
    const float* W2 = (const float*)d_in[4];
    const float* b2 = (const float*)d_in[5];
    float* out = (float*)d_out;

    cudaFuncSetAttribute(moe_mma<true>,  cudaFuncAttributeMaxDynamicSharedMemorySize, SMEM_BYTES);
    cudaFuncSetAttribute(moe_mma<false>, cudaFuncAttributeMaxDynamicSharedMemorySize, SMEM_BYTES);

    cvt_kernel<<<dim3(1024, 2), 256>>>(W1, W2);
    router_kernel<<<NTOK, 256>>>(x, Wr);
    build_kernel<<<NE, 1024>>>();
    moe_mma<true><<<dim3(FD / BN, NSLOT / BM, NE), NTHR, SMEM_BYTES>>>(b1);
    moe_mma<false><<<dim3(HD / BN, NSLOT / BM, NE), NTHR, SMEM_BYTES>>>(nullptr);
    combine_kernel<<<NTOK, 256>>>(b2, out);
}

// round 9
// speedup vs baseline: 1.4126x; 1.4126x over previous
#include <cuda_runtime.h>
#include <cuda_fp16.h>
#include <math.h>
#include <stdint.h>

// ---------------- problem constants -----------------------------------------
#define NTOK 4096
#define HD   1024
#define NE   8
#define FD   4096
#define NSLOT (NTOK * 2)

// ---------------- GEMM tiling ------------------------------------------------
#define BM 128
#define BN 128
#define BK 64
#define STAGES 3
#define NTHR 512

// dynamic smem layout (bytes); stage = A 16KB + B 16KB
#define SM_A    0                        // STAGES x 128x64 fp16
#define SM_B    (STAGES * 16384)         // STAGES x 64x128 fp16
#define SM_BIAS (SM_B + STAGES * 16384)  // 98304 ; 128 fp32
#define SMEM_BYTES (SM_BIAS + 512)       // 98816

// ---------------- scratch (device globals; no allocations) -------------------
__device__ __align__(128) __half g_xh[(size_t)NTOK * HD];
__device__ __align__(128) __half g_w1h[(size_t)NE * HD * FD];
__device__ __align__(128) __half g_w2h[(size_t)NE * FD * HD];
__device__ __align__(128) __half g_h[(size_t)NSLOT * FD];
__device__ float  g_y[(size_t)NSLOT * HD];
__device__ int    g_tok_of_slot[NSLOT];
__device__ int    g_slot_of_tok[NSLOT];
__device__ int    g_expert_of_tok[NSLOT];
__device__ float  g_gate_of_tok[NSLOT];
__device__ int    g_counts[NE];

// ---------------- helpers ----------------------------------------------------
__device__ __forceinline__ uint32_t smem_u32(const void* p) {
    uint32_t a;
    asm("{ .reg .u64 t; cvta.to.shared.u64 t, %1; cvt.u32.u64 %0, t; }" : "=r"(a) : "l"(p));
    return a;
}

__device__ __forceinline__ void cp16(uint32_t dst, const void* src) {
    asm volatile("cp.async.cg.shared.global [%0], [%1], 16;" :: "r"(dst), "l"(src));
}
__device__ __forceinline__ void cp_commit() {
    asm volatile("cp.async.commit_group;" ::: "memory");
}
__device__ __forceinline__ void cp_wait1() {
    asm volatile("cp.async.wait_group 1;" ::: "memory");
}

__device__ __forceinline__ void ldsm4(uint32_t r[4], uint32_t addr) {
    asm volatile("ldmatrix.sync.aligned.m8n8.x4.shared.b16 {%0,%1,%2,%3}, [%4];"
                 : "=r"(r[0]), "=r"(r[1]), "=r"(r[2]), "=r"(r[3]) : "r"(addr));
}
__device__ __forceinline__ void ldsm4t(uint32_t r[4], uint32_t addr) {
    asm volatile("ldmatrix.sync.aligned.m8n8.x4.trans.shared.b16 {%0,%1,%2,%3}, [%4];"
                 : "=r"(r[0]), "=r"(r[1]), "=r"(r[2]), "=r"(r[3]) : "r"(addr));
}

__device__ __forceinline__ void mma16816(float c[4], const uint32_t a[4],
                                         uint32_t b0, uint32_t b1) {
    asm volatile(
        "mma.sync.aligned.m16n8k16.row.col.f32.f16.f16.f32 "
        "{%0,%1,%2,%3}, {%4,%5,%6,%7}, {%8,%9}, {%0,%1,%2,%3};\n"
        : "+f"(c[0]), "+f"(c[1]), "+f"(c[2]), "+f"(c[3])
        : "r"(a[0]), "r"(a[1]), "r"(a[2]), "r"(a[3]), "r"(b0), "r"(b1));
}

__device__ __forceinline__ float gelu_exact(float x) {
    return 0.5f * x * (1.0f + erff(x * 0.70710678118654752440f));
}

// ---------------- stage 1: weight fp16 pre-convert (+zero counts) ------------
__global__ void cvt_kernel(const float* __restrict__ W1,
                           const float* __restrict__ W2) {
    if (blockIdx.x == 0 && blockIdx.y == 0 && threadIdx.x < NE)
        g_counts[threadIdx.x] = 0;
    const float* src = blockIdx.y ? W2 : W1;
    __half* dst = blockIdx.y ? g_w2h : g_w1h;
    const size_t n4 = (size_t)NE * HD * FD / 4;
    const size_t stride = (size_t)gridDim.x * blockDim.x;
    for (size_t i = blockIdx.x * blockDim.x + threadIdx.x; i < n4; i += stride) {
        float4 v = ((const float4*)src)[i];
        __half2 h0 = __floats2half2_rn(v.x, v.y);
        __half2 h1 = __floats2half2_rn(v.z, v.w);
        uint2 u = make_uint2(*(uint32_t*)&h0, *(uint32_t*)&h1);
        ((uint2*)dst)[i] = u;
    }
}

// ---------------- stage 2: router (+ x fp16 convert) -------------------------
__global__ void router_kernel(const float* __restrict__ x,
                              const float* __restrict__ Wr) {
    const int t = blockIdx.x;
    __shared__ float sx[HD];
    __shared__ float slog[NE];

    const float* xr = x + (size_t)t * HD;
    for (int i = threadIdx.x; i < HD; i += blockDim.x) {
        const float v = xr[i];
        sx[i] = v;
        g_xh[(size_t)t * HD + i] = __float2half_rn(v);
    }
    __syncthreads();

    const int w = threadIdx.x >> 5, lane = threadIdx.x & 31;
    if (w < NE) {
        const float* wr = Wr + (size_t)w * HD;
        float s = 0.f;
        for (int i = lane; i < HD; i += 32) s += sx[i] * wr[i];
        #pragma unroll
        for (int o = 16; o > 0; o >>= 1) s += __shfl_xor_sync(0xffffffffu, s, o);
        if (lane == 0) slog[w] = s;
    }
    __syncthreads();

    if (threadIdx.x == 0) {
        int i0 = 0; float v0 = slog[0];
        #pragma unroll
        for (int e = 1; e < NE; e++) if (slog[e] > v0) { v0 = slog[e]; i0 = e; }
        int i1 = -1; float v1 = -INFINITY;
        #pragma unroll
        for (int e = 0; e < NE; e++) {
            if (e == i0) continue;
            if (slog[e] > v1) { v1 = slog[e]; i1 = e; }
        }
        float e1 = expf(v1 - v0);
        float inv = 1.f / (1.f + e1);
        g_expert_of_tok[t * 2 + 0] = i0; g_gate_of_tok[t * 2 + 0] = inv;
        g_expert_of_tok[t * 2 + 1] = i1; g_gate_of_tok[t * 2 + 1] = e1 * inv;
        atomicAdd(&g_counts[i0], 1);
        atomicAdd(&g_counts[i1], 1);
    }
}

// ---------------- stage 3: compaction (offsets fused) ------------------------
__global__ void build_kernel() {
    const int e = blockIdx.x;
    __shared__ int warp_sums[32];
    int base = 0;
    #pragma unroll
    for (int i = 0; i < NE; i++) if (i < e) base += g_counts[i];
    const int lane = threadIdx.x & 31, w = threadIdx.x >> 5;

    for (int t0 = 0; t0 < NTOK; t0 += 1024) {
        const int t = t0 + threadIdx.x;
        int k = -1;
        if (g_expert_of_tok[t * 2 + 0] == e) k = 0;
        else if (g_expert_of_tok[t * 2 + 1] == e) k = 1;
        const int flag = (k >= 0) ? 1 : 0;

        const unsigned bal = __ballot_sync(0xffffffffu, flag);
        const int pre = __popc(bal & ((1u << lane) - 1u));
        if (lane == 0) warp_sums[w] = __popc(bal);
        __syncthreads();
        int woff = 0, total = 0;
        #pragma unroll
        for (int i = 0; i < 32; i++) {
            if (i < w) woff += warp_sums[i];
            total += warp_sums[i];
        }
        if (flag) {
            const int slot = base + woff + pre;
            g_tok_of_slot[slot] = t;
            g_slot_of_tok[t * 2 + k] = slot;
        }
        base += total;
        __syncthreads();
    }
}

// ---------------- stage 4/5: routed fp16 GEMM, fragment double-buffering -----
// FIRST=true : g_h(fp16) = gelu(g_xh[gather] @ W1h[e] + b1[e])   K=HD,  N=FD
// FIRST=false: g_y(fp32) = g_h[contig] @ W2h[e]                  K=FD,  N=HD
template <bool FIRST>
__global__ __launch_bounds__(NTHR, 1) void moe_mma(const float* __restrict__ bias) {
    constexpr int KDIM = FIRST ? HD : FD;
    constexpr int NDIM = FIRST ? FD : HD;
    constexpr int NKT  = KDIM / BK;      // 16 or 64

    const int e  = blockIdx.z;
    const int ne = g_counts[e];
    const int m0 = blockIdx.y * BM;
    if (m0 >= ne) return;
    const int n0 = blockIdx.x * BN;
    int off = 0;
    #pragma unroll
    for (int i = 0; i < NE; i++) if (i < e) off += g_counts[i];

    extern __shared__ char smem[];
    const uint32_t sb = smem_u32(smem);
    const int tid = threadIdx.x;

    if (FIRST && tid < 32)
        ((float4*)(smem + SM_BIAS))[tid] =
            ((const float4*)(bias + (size_t)e * NDIM + n0))[tid];

    const __half* Ab = FIRST ? g_xh : g_h;
    const __half* Wb = (FIRST ? g_w1h : g_w2h) + (size_t)e * KDIM * NDIM;

    // ---- cp.async staging maps (512 threads, 2 granules each per tile) ------
    // A tile 128 rows x 64 halves (128B rows, 8 granules).
    const int ra = tid >> 2, qa = tid & 3;
    int ga = m0 + ra; if (ga > ne - 1) ga = ne - 1;
    const int rowid = FIRST ? g_tok_of_slot[off + ga] : (off + ga);
    const __half* asrc = Ab + (size_t)rowid * KDIM + qa * 16;
    uint32_t ad[2];
    #pragma unroll
    for (int j = 0; j < 2; j++)
        ad[j] = (uint32_t)(ra * 128 + (((qa * 2 + j) ^ (ra & 7)) * 16));

    // B tile 64 rows x 128 halves (256B rows, 16 granules).
    const int rb = tid >> 3, ob = tid & 7;
    const __half* bsrc = Wb + (size_t)rb * NDIM + n0 + ob * 16;
    uint32_t bd[2];
    #pragma unroll
    for (int j = 0; j < 2; j++)
        bd[j] = (uint32_t)(rb * 256 + (((ob * 2 + j) ^ (rb & 7)) * 16));

    // ---- ldmatrix fragment maps: warp grid 4(M) x 4(N), warp tile 32x32 -----
    const int w = tid >> 5, lane = tid & 31;
    const int wm = w & 3, wn = w >> 2;
    const int l16 = lane & 15, lh = lane >> 4;
    const int sel = l16 & 7;
    uint32_t abase[2], xo[4], binner[2];
    #pragma unroll
    for (int mi = 0; mi < 2; mi++)
        abase[mi] = (uint32_t)((wm * 32 + mi * 16 + l16) * 128);
    #pragma unroll
    for (int ks = 0; ks < 4; ks++)
        xo[ks] = (uint32_t)(((2 * ks + lh) ^ sel) * 16);
    #pragma unroll
    for (int nf = 0; nf < 2; nf++)
        binner[nf] = (uint32_t)(l16 * 256 + (((wn * 4 + nf * 2 + lh) ^ sel) * 16));

    float acc[2][4][4];
    #pragma unroll
    for (int mi = 0; mi < 2; mi++)
        #pragma unroll
        for (int ni = 0; ni < 4; ni++)
            #pragma unroll
            for (int q = 0; q < 4; q++) acc[mi][ni][q] = 0.f;

    auto issue_stage = [&](int kt) {
        const int stg = kt % STAGES;
        const uint32_t sa  = sb + SM_A + stg * 16384;
        const uint32_t sbm = sb + SM_B + stg * 16384;
        const __half* ap = asrc + (size_t)kt * BK;
        const __half* bp = bsrc + (size_t)kt * BK * NDIM;
        cp16(sa + ad[0], ap);
        cp16(sa + ad[1], ap + 8);
        cp16(sbm + bd[0], bp);
        cp16(sbm + bd[1], bp + 8);
    };

    // ---- prologue: fill 2 stages ----
    issue_stage(0); cp_commit();
    issue_stage(1); cp_commit();

    // ---- mainloop: per-warp fragment double-buffering across ks -------------
    #pragma unroll 1
    for (int kt = 0; kt < NKT; kt++) {
        cp_wait1();
        __syncthreads();

        const int stg = kt % STAGES;
        const uint32_t sA = sb + SM_A + stg * 16384;
        const uint32_t sB = sb + SM_B + stg * 16384;

        uint32_t af[2][2][4], bf[2][2][4];
        // load ks=0 fragments
        ldsm4 (af[0][0], sA + abase[0] + xo[0]);
        ldsm4 (af[0][1], sA + abase[1] + xo[0]);
        ldsm4t(bf[0][0], sB + binner[0]);
        ldsm4t(bf[0][1], sB + binner[1]);

        if (kt + 2 < NKT) issue_stage(kt + 2);
        cp_commit();

        #pragma unroll
        for (int ks = 0; ks < 4; ks++) {
            const int cur = ks & 1, nxt = cur ^ 1;
            if (ks < 3) {
                ldsm4 (af[nxt][0], sA + abase[0] + xo[ks + 1]);
                ldsm4 (af[nxt][1], sA + abase[1] + xo[ks + 1]);
                ldsm4t(bf[nxt][0], sB + (ks + 1) * 4096 + binner[0]);
                ldsm4t(bf[nxt][1], sB + (ks + 1) * 4096 + binner[1]);
            }
            #pragma unroll
            for (int ni = 0; ni < 4; ni++) {
                const uint32_t b0 = bf[cur][ni >> 1][(ni & 1) * 2 + 0];
                const uint32_t b1 = bf[cur][ni >> 1][(ni & 1) * 2 + 1];
                mma16816(acc[0][ni], af[cur][0], b0, b1);
                mma16816(acc[1][ni], af[cur][1], b0, b1);
            }
        }
    }

    // ---- epilogue ----
    const int rbase = wm * 32 + (lane >> 2);
    const int cbase = wn * 32 + (lane & 3) * 2;
    #pragma unroll
    for (int mi = 0; mi < 2; mi++) {
        #pragma unroll
        for (int hrow = 0; hrow < 2; hrow++) {
            const int mloc = rbase + mi * 16 + hrow * 8;
            const int grow = m0 + mloc;
            if (grow >= ne) continue;
            #pragma unroll
            for (int ni = 0; ni < 4; ni++) {
                const int cr = cbase + ni * 8;
                float v0 = acc[mi][ni][hrow * 2 + 0];
                float v1 = acc[mi][ni][hrow * 2 + 1];
                if (FIRST) {
                    const float2 bv = *(const float2*)(smem + SM_BIAS + cr * 4);
                    v0 = gelu_exact(v0 + bv.x);
                    v1 = gelu_exact(v1 + bv.y);
                    __half2 hv = __floats2half2_rn(v0, v1);
                    *(__half2*)(g_h + (size_t)(off + grow) * NDIM + n0 + cr) = hv;
                } else {
                    *(float2*)(g_y + (size_t)(off + grow) * NDIM + n0 + cr) =
                        make_float2(v0, v1);
                }
            }
        }
    }
}

// ---------------- stage 6: gated combine -------------------------------------
__global__ void combine_kernel(const float* __restrict__ b2,
                               float* __restrict__ out) {
    const int t  = blockIdx.x;
    const int e0 = g_expert_of_tok[t * 2 + 0], e1 = g_expert_of_tok[t * 2 + 1];
    const float gg0 = g_gate_of_tok[t * 2 + 0], gg1 = g_gate_of_tok[t * 2 + 1];
    const int s0 = g_slot_of_tok[t * 2 + 0], s1 = g_slot_of_tok[t * 2 + 1];

    const float4* y0  = (const float4*)(g_y + (size_t)s0 * HD);
    const float4* y1  = (const float4*)(g_y + (size_t)s1 * HD);
    const float4* bb0 = (const float4*)(b2 + (size_t)e0 * HD);
    const float4* bb1 = (const float4*)(b2 + (size_t)e1 * HD);
    float4* o = (float4*)(out + (size_t)t * HD);

    for (int i = threadIdx.x; i < HD / 4; i += blockDim.x) {
        const float4 a = y0[i], b = y1[i], c = bb0[i], d = bb1[i];
        float4 rr;
        rr.x = gg0 * (a.x + c.x) + gg1 * (b.x + d.x);
        rr.y = gg0 * (a.y + c.y) + gg1 * (b.y + d.y);
        rr.z = gg0 * (a.z + c.z) + gg1 * (b.z + d.z);
        rr.w = gg0 * (a.w + c.w) + gg1 * (b.w + d.w);
        o[i] = rr;
    }
}

// ---------------- launch ------------------------------------------------------
extern "C" void kernel_launch(void* const* d_in, const int* in_sizes, int n_in,
                              void* d_out, int out_size) {
    const float* x  = (const float*)d_in[0];
    const float* Wr = (const float*)d_in[1];
    const float* W1 = (const float*)d_in[2];
    const float* b1 = (const float*)d_in[3];
    const float* W2 = (const float*)d_in[4];
    const float* b2 = (const float*)d_in[5];
    float* out = (float*)d_out;

    cudaFuncSetAttribute(moe_mma<true>,  cudaFuncAttributeMaxDynamicSharedMemorySize, SMEM_BYTES);
    cudaFuncSetAttribute(moe_mma<false>, cudaFuncAttributeMaxDynamicSharedMemorySize, SMEM_BYTES);

    cvt_kernel<<<dim3(1024, 2), 256>>>(W1, W2);
    router_kernel<<<NTOK, 256>>>(x, Wr);
    build_kernel<<<NE, 1024>>>();
    moe_mma<true><<<dim3(FD / BN, NSLOT / BM, NE), NTHR, SMEM_BYTES>>>(b1);
    moe_mma<false><<<dim3(HD / BN, NSLOT / BM, NE), NTHR, SMEM_BYTES>>>(nullptr);
    combine_kernel<<<NTOK, 256>>>(b2, out);
}

// round 10
// speedup vs baseline: 1.9017x; 1.3463x over previous
#include <cuda_runtime.h>
#include <cuda_fp16.h>
#include <math.h>
#include <stdint.h>

// ---------------- problem constants -----------------------------------------
#define NTOK 4096
#define HD   1024
#define NE   8
#define FD   4096
#define NSLOT (NTOK * 2)
#define NSLOTP (NSLOT + NE * 128)      // 128-padded per-expert ranges
#define MAXMT 71                        // max total m-tiles (64 + 7 pad)

// ---------------- GEMM tiling (R7 base: fp16 mma + ldmatrix + cp.async) ------
#define BM 128
#define BN 128
#define BK 32
#define STAGES 4
#define NTHR 256

// dynamic smem layout (bytes); stage = A 8KB + B 8KB
#define SM_A    0                       // STAGES x 128x32 fp16
#define SM_B    (STAGES * 8192)         // STAGES x 32x128 fp16
#define SM_BIAS (SM_B + STAGES * 8192)  // 65536 ; 128 fp32
#define SMEM_BYTES (SM_BIAS + 512)      // 66048  (2 CTAs/SM -> 132KB)

// ---------------- scratch (device globals; no allocations) -------------------
__device__ __align__(128) __half g_xh[(size_t)NTOK * HD];
__device__ __align__(128) __half g_w1h[(size_t)NE * HD * FD];
__device__ __align__(128) __half g_w2h[(size_t)NE * FD * HD];
__device__ __align__(128) __half g_h[(size_t)NSLOTP * FD];
__device__ float  g_y[(size_t)NSLOTP * HD];
__device__ int    g_tok_of_slot[NSLOTP];
__device__ int    g_slot_of_tok[NSLOT];
__device__ int    g_expert_of_tok[NSLOT];
__device__ float  g_gate_of_tok[NSLOT];
__device__ int    g_counts[NE];

// ---------------- helpers ----------------------------------------------------
__device__ __forceinline__ uint32_t smem_u32(const void* p) {
    uint32_t a;
    asm("{ .reg .u64 t; cvta.to.shared.u64 t, %1; cvt.u32.u64 %0, t; }" : "=r"(a) : "l"(p));
    return a;
}

__device__ __forceinline__ void cp16(uint32_t dst, const void* src) {
    asm volatile("cp.async.cg.shared.global [%0], [%1], 16;" :: "r"(dst), "l"(src));
}
__device__ __forceinline__ void cp_commit() {
    asm volatile("cp.async.commit_group;" ::: "memory");
}
__device__ __forceinline__ void cp_wait2() {
    asm volatile("cp.async.wait_group 2;" ::: "memory");
}

__device__ __forceinline__ void ldsm4(uint32_t r[4], uint32_t addr) {
    asm volatile("ldmatrix.sync.aligned.m8n8.x4.shared.b16 {%0,%1,%2,%3}, [%4];"
                 : "=r"(r[0]), "=r"(r[1]), "=r"(r[2]), "=r"(r[3]) : "r"(addr));
}
__device__ __forceinline__ void ldsm4t(uint32_t r[4], uint32_t addr) {
    asm volatile("ldmatrix.sync.aligned.m8n8.x4.trans.shared.b16 {%0,%1,%2,%3}, [%4];"
                 : "=r"(r[0]), "=r"(r[1]), "=r"(r[2]), "=r"(r[3]) : "r"(addr));
}

__device__ __forceinline__ void mma16816(float c[4], const uint32_t a[4],
                                         uint32_t b0, uint32_t b1) {
    asm volatile(
        "mma.sync.aligned.m16n8k16.row.col.f32.f16.f16.f32 "
        "{%0,%1,%2,%3}, {%4,%5,%6,%7}, {%8,%9}, {%0,%1,%2,%3};\n"
        : "+f"(c[0]), "+f"(c[1]), "+f"(c[2]), "+f"(c[3])
        : "r"(a[0]), "r"(a[1]), "r"(a[2]), "r"(a[3]), "r"(b0), "r"(b1));
}

__device__ __forceinline__ float gelu_exact(float x) {
    return 0.5f * x * (1.0f + erff(x * 0.70710678118654752440f));
}

// ---------------- stage 1: weight fp16 pre-convert (+zero counts) ------------
__global__ void cvt_kernel(const float* __restrict__ W1,
                           const float* __restrict__ W2) {
    if (blockIdx.x == 0 && blockIdx.y == 0 && threadIdx.x < NE)
        g_counts[threadIdx.x] = 0;
    const float* src = blockIdx.y ? W2 : W1;
    __half* dst = blockIdx.y ? g_w2h : g_w1h;
    const size_t n4 = (size_t)NE * HD * FD / 4;
    const size_t stride = (size_t)gridDim.x * blockDim.x;
    for (size_t i = blockIdx.x * blockDim.x + threadIdx.x; i < n4; i += stride) {
        float4 v = ((const float4*)src)[i];
        __half2 h0 = __floats2half2_rn(v.x, v.y);
        __half2 h1 = __floats2half2_rn(v.z, v.w);
        uint2 u = make_uint2(*(uint32_t*)&h0, *(uint32_t*)&h1);
        ((uint2*)dst)[i] = u;
    }
}

// ---------------- stage 2: router (+ x fp16 convert) -------------------------
__global__ void router_kernel(const float* __restrict__ x,
                              const float* __restrict__ Wr) {
    const int t = blockIdx.x;
    __shared__ float sx[HD];
    __shared__ float slog[NE];

    const float* xr = x + (size_t)t * HD;
    for (int i = threadIdx.x; i < HD; i += blockDim.x) {
        const float v = xr[i];
        sx[i] = v;
        g_xh[(size_t)t * HD + i] = __float2half_rn(v);
    }
    __syncthreads();

    const int w = threadIdx.x >> 5, lane = threadIdx.x & 31;
    if (w < NE) {
        const float* wr = Wr + (size_t)w * HD;
        float s = 0.f;
        for (int i = lane; i < HD; i += 32) s += sx[i] * wr[i];
        #pragma unroll
        for (int o = 16; o > 0; o >>= 1) s += __shfl_xor_sync(0xffffffffu, s, o);
        if (lane == 0) slog[w] = s;
    }
    __syncthreads();

    if (threadIdx.x == 0) {
        int i0 = 0; float v0 = slog[0];
        #pragma unroll
        for (int e = 1; e < NE; e++) if (slog[e] > v0) { v0 = slog[e]; i0 = e; }
        int i1 = -1; float v1 = -INFINITY;
        #pragma unroll
        for (int e = 0; e < NE; e++) {
            if (e == i0) continue;
            if (slog[e] > v1) { v1 = slog[e]; i1 = e; }
        }
        float e1 = expf(v1 - v0);
        float inv = 1.f / (1.f + e1);
        g_expert_of_tok[t * 2 + 0] = i0; g_gate_of_tok[t * 2 + 0] = inv;
        g_expert_of_tok[t * 2 + 1] = i1; g_gate_of_tok[t * 2 + 1] = e1 * inv;
        atomicAdd(&g_counts[i0], 1);
        atomicAdd(&g_counts[i1], 1);
    }
}

// ---------------- stage 3: compaction into 128-padded ranges -----------------
__global__ void build_kernel() {
    const int e = blockIdx.x;
    __shared__ int warp_sums[32];
    int base = 0;
    #pragma unroll
    for (int i = 0; i < NE; i++)
        if (i < e) base += ((g_counts[i] + 127) >> 7) << 7;   // padded offset
    const int lane = threadIdx.x & 31, w = threadIdx.x >> 5;

    for (int t0 = 0; t0 < NTOK; t0 += 1024) {
        const int t = t0 + threadIdx.x;
        int k = -1;
        if (g_expert_of_tok[t * 2 + 0] == e) k = 0;
        else if (g_expert_of_tok[t * 2 + 1] == e) k = 1;
        const int flag = (k >= 0) ? 1 : 0;

        const unsigned bal = __ballot_sync(0xffffffffu, flag);
        const int pre = __popc(bal & ((1u << lane) - 1u));
        if (lane == 0) warp_sums[w] = __popc(bal);
        __syncthreads();
        int woff = 0, total = 0;
        #pragma unroll
        for (int i = 0; i < 32; i++) {
            if (i < w) woff += warp_sums[i];
            total += warp_sums[i];
        }
        if (flag) {
            const int slot = base + woff + pre;
            g_tok_of_slot[slot] = t;
            g_slot_of_tok[t * 2 + k] = slot;
        }
        base += total;
        __syncthreads();
    }
}

// ---------------- stage 4/5: routed fp16 GEMM (flattened m-tiles + skew) -----
// FIRST=true : g_h(fp16) = gelu(g_xh[gather] @ W1h[e] + b1[e])   K=HD,  N=FD
// FIRST=false: g_y(fp32) = g_h[padded] @ W2h[e]                  K=FD,  N=HD
template <bool FIRST>
__global__ __launch_bounds__(NTHR, 2) void moe_mma(const float* __restrict__ bias) {
    constexpr int KDIM = FIRST ? HD : FD;
    constexpr int NDIM = FIRST ? FD : HD;
    constexpr int NKT  = KDIM / BK;

    // ---- flattened m-tile decode: blockIdx.y -> (expert, m0, padded off) ----
    const int j = blockIdx.y;
    int e = -1, m0 = 0, off = 0, ne = 0;
    {
        int cum = 0, poff = 0;
        #pragma unroll
        for (int i = 0; i < NE; i++) {
            const int c  = g_counts[i];
            const int mt = (c + BM - 1) >> 7;
            if (e < 0 && j < cum + mt) { e = i; m0 = (j - cum) << 7; off = poff; ne = c; }
            cum  += mt;
            poff += mt << 7;
        }
    }
    if (e < 0) return;
    const int n0 = blockIdx.x * BN;

    extern __shared__ char smem[];
    const uint32_t sb = smem_u32(smem);
    const int tid = threadIdx.x;

    if (FIRST && tid < 32)
        ((float4*)(smem + SM_BIAS))[tid] =
            ((const float4*)(bias + (size_t)e * NDIM + n0))[tid];

    const __half* Ab = FIRST ? g_xh : g_h;
    const __half* Wb = (FIRST ? g_w1h : g_w2h) + (size_t)e * KDIM * NDIM;

    // ---- cp.async staging maps (R7-validated) ----
    const int r = tid >> 1, hs = tid & 1;
    int ga = m0 + r; if (ga > ne - 1) ga = ne - 1;
    const int rowid = FIRST ? g_tok_of_slot[off + ga] : (off + ga);
    const __half* asrc = Ab + (size_t)rowid * KDIM + hs * 16;
    const uint32_t ad0 = (uint32_t)(r * 64 + (((hs * 2 + 0) ^ ((r >> 1) & 3)) * 16));
    const uint32_t ad1 = (uint32_t)(r * 64 + (((hs * 2 + 1) ^ ((r >> 1) & 3)) * 16));

    const int kk = tid >> 3, lane8 = tid & 7;
    const __half* bsrc = Wb + (size_t)kk * NDIM + n0 + lane8 * 8;
    uint32_t bd[2];
    #pragma unroll
    for (int jj = 0; jj < 2; jj++)
        bd[jj] = (uint32_t)(kk * 256 + (((lane8 + 8 * jj) ^ (kk & 7)) * 16));

    // ---- ldmatrix fragment maps: warp grid 2(M) x 4(N), warp tile 64x32 ----
    const int w = tid >> 5, lane = tid & 31;
    const int wm = w & 1, wn = w >> 1;
    const int l16 = lane & 15, lh = lane >> 4;
    uint32_t ao[2][4], bo[2][2];
    #pragma unroll
    for (int ks = 0; ks < 2; ks++) {
        #pragma unroll
        for (int mi = 0; mi < 4; mi++) {
            const int row = wm * 64 + mi * 16 + l16;
            const int gr  = ks * 2 + lh;
            ao[ks][mi] = (uint32_t)(row * 64 + ((gr ^ ((row >> 1) & 3)) * 16));
        }
        #pragma unroll
        for (int nb = 0; nb < 2; nb++) {
            const int kr = ks * 16 + l16;
            const int ng = wn * 4 + nb * 2 + lh;
            bo[ks][nb] = (uint32_t)(kr * 256 + ((ng ^ (kr & 7)) * 16));
        }
    }

    float acc[4][4][4];
    #pragma unroll
    for (int mi = 0; mi < 4; mi++)
        #pragma unroll
        for (int ni = 0; ni < 4; ni++)
            #pragma unroll
            for (int q = 0; q < 4; q++) acc[mi][ni][q] = 0.f;

    auto issue_stage = [&](int kt) {
        const uint32_t sa  = sb + SM_A + (kt & (STAGES - 1)) * 8192;
        const uint32_t sbm = sb + SM_B + (kt & (STAGES - 1)) * 8192;
        const __half* ap = asrc + (size_t)kt * BK;
        cp16(sa + ad0, ap);
        cp16(sa + ad1, ap + 8);
        const __half* bp = bsrc + (size_t)kt * BK * NDIM;
        cp16(sbm + bd[0], bp);
        cp16(sbm + bd[1], bp + 64);
    };

    // ---- prologue: fill 3 stages ----
    #pragma unroll
    for (int s = 0; s < STAGES - 1; s++) { issue_stage(s); cp_commit(); }

    // ---- phase skew: anti-phase the co-resident CTA pair --------------------
    {
        const int lbid = blockIdx.x + gridDim.x * blockIdx.y;
        if ((lbid / 148) & 1) {
            const long long t0 = clock64();
            while (clock64() - t0 < 480) {}
        }
    }

    // ---- mainloop (R7 structure) ----
    #pragma unroll 1
    for (int kt = 0; kt < NKT; kt++) {
        cp_wait2();
        __syncthreads();

        const int buf = kt & (STAGES - 1);
        const uint32_t sA = sb + SM_A + buf * 8192;
        const uint32_t sB = sb + SM_B + buf * 8192;
        #pragma unroll
        for (int ks = 0; ks < 2; ks++) {
            uint32_t af[4][4], bf[2][4];
            ldsm4 (af[0], sA + ao[ks][0]);
            ldsm4 (af[1], sA + ao[ks][1]);
            ldsm4 (af[2], sA + ao[ks][2]);
            ldsm4 (af[3], sA + ao[ks][3]);
            ldsm4t(bf[0], sB + bo[ks][0]);
            ldsm4t(bf[1], sB + bo[ks][1]);
            #pragma unroll
            for (int nb = 0; nb < 2; nb++) {
                #pragma unroll
                for (int mi = 0; mi < 4; mi++) {
                    mma16816(acc[mi][nb * 2 + 0], af[mi], bf[nb][0], bf[nb][1]);
                    mma16816(acc[mi][nb * 2 + 1], af[mi], bf[nb][2], bf[nb][3]);
                }
            }
        }

        if (kt + STAGES - 1 < NKT) issue_stage(kt + STAGES - 1);
        cp_commit();
    }

    // ---- epilogue ----
    const int rbase = wm * 64 + (lane >> 2);
    const int cbase = wn * 32 + (lane & 3) * 2;
    #pragma unroll
    for (int mi = 0; mi < 4; mi++) {
        #pragma unroll
        for (int hrow = 0; hrow < 2; hrow++) {
            const int mloc = rbase + mi * 16 + hrow * 8;
            const int grow = m0 + mloc;
            if (grow >= ne) continue;
            #pragma unroll
            for (int ni = 0; ni < 4; ni++) {
                const int cr = cbase + ni * 8;
                float v0 = acc[mi][ni][hrow * 2 + 0];
                float v1 = acc[mi][ni][hrow * 2 + 1];
                if (FIRST) {
                    const float2 bv = *(const float2*)(smem + SM_BIAS + cr * 4);
                    v0 = gelu_exact(v0 + bv.x);
                    v1 = gelu_exact(v1 + bv.y);
                    __half2 hv = __floats2half2_rn(v0, v1);
                    *(__half2*)(g_h + (size_t)(off + grow) * NDIM + n0 + cr) = hv;
                } else {
                    *(float2*)(g_y + (size_t)(off + grow) * NDIM + n0 + cr) =
                        make_float2(v0, v1);
                }
            }
        }
    }
}

// ---------------- stage 6: gated combine -------------------------------------
__global__ void combine_kernel(const float* __restrict__ b2,
                               float* __restrict__ out) {
    const int t  = blockIdx.x;
    const int e0 = g_expert_of_tok[t * 2 + 0], e1 = g_expert_of_tok[t * 2 + 1];
    const float gg0 = g_gate_of_tok[t * 2 + 0], gg1 = g_gate_of_tok[t * 2 + 1];
    const int s0 = g_slot_of_tok[t * 2 + 0], s1 = g_slot_of_tok[t * 2 + 1];

    const float4* y0  = (const float4*)(g_y + (size_t)s0 * HD);
    const float4* y1  = (const float4*)(g_y + (size_t)s1 * HD);
    const float4* bb0 = (const float4*)(b2 + (size_t)e0 * HD);
    const float4* bb1 = (const float4*)(b2 + (size_t)e1 * HD);
    float4* o = (float4*)(out + (size_t)t * HD);

    for (int i = threadIdx.x; i < HD / 4; i += blockDim.x) {
        const float4 a = y0[i], b = y1[i], c = bb0[i], d = bb1[i];
        float4 rr;
        rr.x = gg0 * (a.x + c.x) + gg1 * (b.x + d.x);
        rr.y = gg0 * (a.y + c.y) + gg1 * (b.y + d.y);
        rr.z = gg0 * (a.z + c.z) + gg1 * (b.z + d.z);
        rr.w = gg0 * (a.w + c.w) + gg1 * (b.w + d.w);
        o[i] = rr;
    }
}

// ---------------- launch ------------------------------------------------------
extern "C" void kernel_launch(void* const* d_in, const int* in_sizes, int n_in,
                              void* d_out, int out_size) {
    const float* x  = (const float*)d_in[0];
    const float* Wr = (const float*)d_in[1];
    const float* W1 = (const float*)d_in[2];
    const float* b1 = (const float*)d_in[3];
    const float* W2 = (const float*)d_in[4];
    const float* b2 = (const float*)d_in[5];
    float* out = (float*)d_out;

    cudaFuncSetAttribute(moe_mma<true>,  cudaFuncAttributeMaxDynamicSharedMemorySize, SMEM_BYTES);
    cudaFuncSetAttribute(moe_mma<false>, cudaFuncAttributeMaxDynamicSharedMemorySize, SMEM_BYTES);

    cvt_kernel<<<dim3(1024, 2), 256>>>(W1, W2);
    router_kernel<<<NTOK, 256>>>(x, Wr);
    build_kernel<<<NE, 1024>>>();
    moe_mma<true><<<dim3(FD / BN, MAXMT), NTHR, SMEM_BYTES>>>(b1);
    moe_mma<false><<<dim3(HD / BN, MAXMT), NTHR, SMEM_BYTES>>>(nullptr);
    combine_kernel<<<NTOK, 256>>>(b2, out);
}